// round 1
// baseline (speedup 1.0000x reference)
#include <cuda_runtime.h>
#include <cuda_bf16.h>
#include <math.h>

// Problem constants (fixed shapes per reference)
constexpr int T_   = 4096;   // tokens
constexpr int E_   = 8;      // experts
constexpr int H_   = 1024;   // hidden
constexpr int I_   = 2048;   // intermediate
constexpr int CAP  = 4096;   // per-expert capacity (worst case: all tokens pick this expert)

// ---------------------------------------------------------------------------
// Scratch (device globals — allocation inside kernel_launch is forbidden)
// ---------------------------------------------------------------------------
__device__ int   g_count[E_];            // tokens routed to each expert
__device__ int   g_tok[E_ * CAP];        // token id per (expert, slot)
__device__ int   g_slot[T_ * 2];         // slot index for (token, k)
__device__ float g_wt[T_ * 2];           // renormalized weight for (token, k)

__device__ float g_gu[(size_t)E_ * CAP * 2 * I_];  // [slot, 2I] gate|up   (512 MB)
__device__ float g_h [(size_t)E_ * CAP * I_];      // [slot, I]  silu(g)*u (256 MB)
__device__ float g_y [(size_t)E_ * CAP * H_];      // [slot, H]  expert out(128 MB)

// ---------------------------------------------------------------------------
// 0) reset per-launch state
// ---------------------------------------------------------------------------
__global__ void init_kernel() {
    if (threadIdx.x < E_) g_count[threadIdx.x] = 0;
}

// ---------------------------------------------------------------------------
// 1) router: top-2 of 8 logits, renormalized softmax weights, scatter to
//    per-expert compacted lists. One thread per token.
//    renorm weight: p0/(p0+p1) = 1/(1+exp(l1-l0))  (softmax Z cancels)
// ---------------------------------------------------------------------------
__global__ void router_kernel(const float* __restrict__ logits) {
    int t = blockIdx.x * blockDim.x + threadIdx.x;
    if (t >= T_) return;
    float l[E_];
#pragma unroll
    for (int e = 0; e < E_; e++) l[e] = logits[t * E_ + e];

    int b0 = 0; float m0 = l[0];
#pragma unroll
    for (int e = 1; e < E_; e++) if (l[e] > m0) { m0 = l[e]; b0 = e; }
    int b1 = -1; float m1 = -3.0e38f;
#pragma unroll
    for (int e = 0; e < E_; e++) if (e != b0 && l[e] > m1) { m1 = l[e]; b1 = e; }

    float w0 = 1.0f / (1.0f + expf(m1 - m0));
    float w1 = 1.0f - w0;

    int p0 = atomicAdd(&g_count[b0], 1);
    g_tok[b0 * CAP + p0] = t;
    g_slot[2 * t + 0]    = b0 * CAP + p0;
    g_wt  [2 * t + 0]    = w0;

    int p1 = atomicAdd(&g_count[b1], 1);
    g_tok[b1 * CAP + p1] = t;
    g_slot[2 * t + 1]    = b1 * CAP + p1;
    g_wt  [2 * t + 1]    = w1;
}

// ---------------------------------------------------------------------------
// 2) NT SGEMM core:  C[eCAP+m, n] = sum_k A[m,k] * B[e,n,k]
//    A is gathered via g_tok when GATHER (GEMM1: A = x), else direct padded
//    rows (GEMM2: A = g_h). 128x128x8 tile, 256 threads, 8x8 microtile,
//    register-prefetch single smem buffer. Blocks past the expert's row
//    count exit immediately.
// ---------------------------------------------------------------------------
template <bool GATHER>
__global__ void __launch_bounds__(256)
gemm_nt_kernel(const float* __restrict__ A,
               const float* __restrict__ B,
               float* __restrict__ C,
               int N, int Kd)
{
    const int e    = blockIdx.z;
    const int cnt  = g_count[e];
    const int row0 = blockIdx.y * 128;
    if (row0 >= cnt) return;
    const int col0 = blockIdx.x * 128;

    __shared__ float As[8][128];
    __shared__ float Bs[8][128];

    const int tid = threadIdx.x;
    const int tx  = tid % 16;          // micro-tile col group
    const int ty  = tid / 16;          // micro-tile row group
    const int lr  = tid >> 1;          // load row within tile (0..127)
    const int lk  = (tid & 1) * 4;     // load k offset (0 or 4)

    // A load pointer (row-major, K contiguous)
    const float* aptr;
    bool a_valid = true;
    if (GATHER) {
        int r = row0 + lr;
        if (r < cnt) aptr = A + (size_t)g_tok[e * CAP + r] * Kd + lk;
        else { a_valid = false; aptr = A; }
    } else {
        aptr = A + (size_t)(e * CAP + row0 + lr) * Kd + lk;
    }
    const float* bptr = B + (size_t)e * N * Kd + (size_t)(col0 + lr) * Kd + lk;

    float acc[8][8];
#pragma unroll
    for (int i = 0; i < 8; i++)
#pragma unroll
        for (int j = 0; j < 8; j++) acc[i][j] = 0.0f;

    float4 aReg = a_valid ? *(const float4*)aptr : make_float4(0, 0, 0, 0);
    float4 bReg = *(const float4*)bptr;

    const int kTiles = Kd / 8;
    for (int kt = 0; kt < kTiles; kt++) {
        As[lk + 0][lr] = aReg.x; As[lk + 1][lr] = aReg.y;
        As[lk + 2][lr] = aReg.z; As[lk + 3][lr] = aReg.w;
        Bs[lk + 0][lr] = bReg.x; Bs[lk + 1][lr] = bReg.y;
        Bs[lk + 2][lr] = bReg.z; Bs[lk + 3][lr] = bReg.w;
        __syncthreads();

        if (kt + 1 < kTiles) {
            aReg = a_valid ? *(const float4*)(aptr + (size_t)(kt + 1) * 8)
                           : make_float4(0, 0, 0, 0);
            bReg = *(const float4*)(bptr + (size_t)(kt + 1) * 8);
        }

#pragma unroll
        for (int k = 0; k < 8; k++) {
            float a[8], b[8];
            *(float4*)&a[0] = *(const float4*)&As[k][ty * 8];
            *(float4*)&a[4] = *(const float4*)&As[k][ty * 8 + 4];
            *(float4*)&b[0] = *(const float4*)&Bs[k][tx * 8];
            *(float4*)&b[4] = *(const float4*)&Bs[k][tx * 8 + 4];
#pragma unroll
            for (int i = 0; i < 8; i++)
#pragma unroll
                for (int j = 0; j < 8; j++)
                    acc[i][j] = fmaf(a[i], b[j], acc[i][j]);
        }
        __syncthreads();
    }

    // store (padded rows beyond cnt hold zeros/garbage and are never read)
#pragma unroll
    for (int i = 0; i < 8; i++) {
        int r = row0 + ty * 8 + i;
        float* cp = C + (size_t)(e * CAP + r) * N + col0 + tx * 8;
        *(float4*)cp       = make_float4(acc[i][0], acc[i][1], acc[i][2], acc[i][3]);
        *(float4*)(cp + 4) = make_float4(acc[i][4], acc[i][5], acc[i][6], acc[i][7]);
    }
}

// ---------------------------------------------------------------------------
// 3) h = silu(gate) * up, one block per active slot row
// ---------------------------------------------------------------------------
__global__ void act_kernel() {
    int row = blockIdx.x;                // 0 .. E*CAP-1
    int e = row / CAP, r = row % CAP;
    if (r >= g_count[e]) return;
    const float* gu = g_gu + (size_t)row * (2 * I_);
    float*       h  = g_h  + (size_t)row * I_;
    for (int j = threadIdx.x; j < I_; j += blockDim.x) {
        float g = gu[j];
        float u = gu[I_ + j];
        h[j] = (g / (1.0f + expf(-g))) * u;
    }
}

// ---------------------------------------------------------------------------
// 4) combine: out[t] = w0*y[slot0] + w1*y[slot1]   (no atomics, deterministic)
// ---------------------------------------------------------------------------
__global__ void combine_kernel(float* __restrict__ out) {
    int t = blockIdx.x;
    int   s0 = g_slot[2 * t + 0], s1 = g_slot[2 * t + 1];
    float w0 = g_wt [2 * t + 0], w1 = g_wt [2 * t + 1];
    const float* y0 = g_y + (size_t)s0 * H_;
    const float* y1 = g_y + (size_t)s1 * H_;
    float*       o  = out + (size_t)t * H_;
    for (int j = threadIdx.x; j < H_; j += blockDim.x)
        o[j] = w0 * y0[j] + w1 * y1[j];
}

// ---------------------------------------------------------------------------
// launch
// ---------------------------------------------------------------------------
extern "C" void kernel_launch(void* const* d_in, const int* in_sizes, int n_in,
                              void* d_out, int out_size)
{
    const float* x      = (const float*)d_in[0];   // [T, H]
    const float* logits = (const float*)d_in[1];   // [T, E]
    const float* w13    = (const float*)d_in[2];   // [E, 2I, H]
    const float* w2     = (const float*)d_in[3];   // [E, H, I]
    float* out = (float*)d_out;                    // [T, H]

    float *gu, *h, *y;
    cudaGetSymbolAddress((void**)&gu, g_gu);
    cudaGetSymbolAddress((void**)&h,  g_h);
    cudaGetSymbolAddress((void**)&y,  g_y);

    init_kernel  <<<1, 32>>>();
    router_kernel<<<T_ / 256, 256>>>(logits);

    // GEMM1: gu[slot, 0:2I] = x[tok] @ w13[e]^T   (N = 2I = 4096, K = H = 1024)
    gemm_nt_kernel<true><<<dim3(2 * I_ / 128, CAP / 128, E_), 256>>>(x, w13, gu, 2 * I_, H_);

    // activation
    act_kernel<<<E_ * CAP, 256>>>();

    // GEMM2: y[slot, 0:H] = h @ w2[e]^T           (N = H = 1024, K = I = 2048)
    gemm_nt_kernel<false><<<dim3(H_ / 128, CAP / 128, E_), 256>>>(h, w2, y, H_, I_);

    // weighted combine into output
    combine_kernel<<<T_, 256>>>(out);
}

// round 3
// speedup vs baseline: 2.9474x; 2.9474x over previous
#include <cuda_runtime.h>
#include <cuda_fp16.h>
#include <math.h>
#include <stdint.h>

// Problem constants
constexpr int T_  = 4096;
constexpr int E_  = 8;
constexpr int H_  = 1024;
constexpr int I_  = 2048;
constexpr int CAP = 4096;

// ---------------------------------------------------------------------------
// Scratch (device globals)
// ---------------------------------------------------------------------------
__device__ int   g_count[E_];
__device__ int   g_tok[E_ * CAP];
__device__ int   g_slot[T_ * 2];
__device__ float g_wt[T_ * 2];

__device__ __half g_w13h[(size_t)E_ * 2 * I_ * H_];  // permuted rows: 2j=gate_j, 2j+1=up_j
__device__ __half g_w13l[(size_t)E_ * 2 * I_ * H_];
__device__ __half g_w2h [(size_t)E_ * H_ * I_];
__device__ __half g_w2l [(size_t)E_ * H_ * I_];
__device__ __half g_xh  [(size_t)T_ * H_];
__device__ __half g_xl  [(size_t)T_ * H_];
__device__ __half g_hh  [(size_t)E_ * CAP * I_];
__device__ __half g_hl  [(size_t)E_ * CAP * I_];
__device__ float  g_y   [(size_t)E_ * CAP * H_];

// ---------------------------------------------------------------------------
// helpers
// ---------------------------------------------------------------------------
__device__ __forceinline__ uint32_t smem_u32(const void* p) {
    uint32_t a;
    asm("{ .reg .u64 t; cvta.to.shared.u64 t, %1; cvt.u32.u64 %0, t; }" : "=r"(a) : "l"(p));
    return a;
}
__device__ __forceinline__ void cp_async16(uint32_t dst, const void* src, int src_bytes) {
    asm volatile("cp.async.cg.shared.global [%0], [%1], 16, %2;"
                 :: "r"(dst), "l"(src), "r"(src_bytes));
}
#define CP_COMMIT() asm volatile("cp.async.commit_group;" ::: "memory")
#define CP_WAIT1()  asm volatile("cp.async.wait_group 1;" ::: "memory")

__device__ __forceinline__ void ldm_x4(uint32_t addr, uint32_t* r) {
    asm volatile("ldmatrix.sync.aligned.m8n8.x4.shared.b16 {%0,%1,%2,%3}, [%4];"
                 : "=r"(r[0]), "=r"(r[1]), "=r"(r[2]), "=r"(r[3]) : "r"(addr));
}
__device__ __forceinline__ void mma16816(float* c, const uint32_t* a, const uint32_t* b) {
    asm volatile("mma.sync.aligned.m16n8k16.row.col.f32.f16.f16.f32 "
                 "{%0,%1,%2,%3}, {%4,%5,%6,%7}, {%8,%9}, {%0,%1,%2,%3};"
                 : "+f"(c[0]), "+f"(c[1]), "+f"(c[2]), "+f"(c[3])
                 : "r"(a[0]), "r"(a[1]), "r"(a[2]), "r"(a[3]), "r"(b[0]), "r"(b[1]));
}

// SMEM: 3 stages x (A 16KB + B 16KB); K-chunk = 64 halves = 128B rows, SW128 swizzle
static constexpr int STAGE_BYTES = 32768;
static constexpr uint32_t SMEM_BYTES = 3 * STAGE_BYTES;   // 98304

// ---------------------------------------------------------------------------
// router / init / combine
// ---------------------------------------------------------------------------
__global__ void init_kernel() { if (threadIdx.x < E_) g_count[threadIdx.x] = 0; }

__global__ void router_kernel(const float* __restrict__ logits) {
    int t = blockIdx.x * blockDim.x + threadIdx.x;
    if (t >= T_) return;
    float l[E_];
#pragma unroll
    for (int e = 0; e < E_; e++) l[e] = logits[t * E_ + e];
    int b0 = 0; float m0 = l[0];
#pragma unroll
    for (int e = 1; e < E_; e++) if (l[e] > m0) { m0 = l[e]; b0 = e; }
    int b1 = -1; float m1 = -3.0e38f;
#pragma unroll
    for (int e = 0; e < E_; e++) if (e != b0 && l[e] > m1) { m1 = l[e]; b1 = e; }
    float w0 = 1.0f / (1.0f + expf(m1 - m0));
    float w1 = 1.0f - w0;
    int p0 = atomicAdd(&g_count[b0], 1);
    g_tok[b0 * CAP + p0] = t;  g_slot[2 * t + 0] = b0 * CAP + p0;  g_wt[2 * t + 0] = w0;
    int p1 = atomicAdd(&g_count[b1], 1);
    g_tok[b1 * CAP + p1] = t;  g_slot[2 * t + 1] = b1 * CAP + p1;  g_wt[2 * t + 1] = w1;
}

__global__ void combine_kernel(float* __restrict__ out) {
    int t = blockIdx.x;
    int   s0 = g_slot[2 * t + 0], s1 = g_slot[2 * t + 1];
    float w0 = g_wt [2 * t + 0], w1 = g_wt [2 * t + 1];
    const float* y0 = g_y + (size_t)s0 * H_;
    const float* y1 = g_y + (size_t)s1 * H_;
    float* o = out + (size_t)t * H_;
    for (int j = threadIdx.x; j < H_; j += blockDim.x)
        o[j] = w0 * y0[j] + w1 * y1[j];
}

// ---------------------------------------------------------------------------
// fp32 -> fp16 hi/lo splits
// ---------------------------------------------------------------------------
__global__ void split_kernel(const float* __restrict__ s, __half* __restrict__ h,
                             __half* __restrict__ l, size_t n4) {
    size_t i = blockIdx.x * (size_t)blockDim.x + threadIdx.x;
    if (i >= n4) return;
    float4 v = ((const float4*)s)[i];
    __half h0 = __float2half_rn(v.x), h1 = __float2half_rn(v.y),
           h2 = __float2half_rn(v.z), h3 = __float2half_rn(v.w);
    ((__half2*)h)[2 * i]     = __halves2half2(h0, h1);
    ((__half2*)h)[2 * i + 1] = __halves2half2(h2, h3);
    ((__half2*)l)[2 * i]     = __halves2half2(__float2half_rn(v.x - __half2float(h0)),
                                              __float2half_rn(v.y - __half2float(h1)));
    ((__half2*)l)[2 * i + 1] = __halves2half2(__float2half_rn(v.z - __half2float(h2)),
                                              __float2half_rn(v.w - __half2float(h3)));
}

__global__ void split_w13_kernel(const float* __restrict__ s, __half* __restrict__ h,
                                 __half* __restrict__ l) {
    size_t i = blockIdx.x * (size_t)blockDim.x + threadIdx.x;  // float4 index
    size_t total = (size_t)E_ * 2 * I_ * H_ / 4;
    if (i >= total) return;
    float4 v = ((const float4*)s)[i];
    size_t hp  = i % (H_ / 4);
    size_t row = i / (H_ / 4);
    size_t e  = row / (2 * I_);
    size_t jj = row % (2 * I_);
    size_t r  = (jj < (size_t)I_) ? (2 * jj) : (2 * (jj - I_) + 1);
    size_t o  = (e * (size_t)(2 * I_) + r) * (H_ / 4) + hp;
    __half h0 = __float2half_rn(v.x), h1 = __float2half_rn(v.y),
           h2 = __float2half_rn(v.z), h3 = __float2half_rn(v.w);
    ((__half2*)h)[2 * o]     = __halves2half2(h0, h1);
    ((__half2*)h)[2 * o + 1] = __halves2half2(h2, h3);
    ((__half2*)l)[2 * o]     = __halves2half2(__float2half_rn(v.x - __half2float(h0)),
                                              __float2half_rn(v.y - __half2float(h1)));
    ((__half2*)l)[2 * o + 1] = __halves2half2(__float2half_rn(v.z - __half2float(h2)),
                                              __float2half_rn(v.w - __half2float(h3)));
}

// ---------------------------------------------------------------------------
// HMMA GEMM: per expert z, C[128x128 tile] = A[128,K] @ B[N,K]^T
// fp16x3 passes: Ah*Bh + Al*Bh + Ah*Bl (fp32 accum in registers).
// GATHER: A rows via g_tok.  FUSE: epilogue silu(g)*u -> h hi/lo (gate/up
// interleaved in B columns so each accum pair (c0,c1) is one (g,u) pair).
// ---------------------------------------------------------------------------
template <int KD, int NTOT, bool GATHER, bool FUSE>
__global__ void __launch_bounds__(256)
moe_gemm(const __half* __restrict__ Ah, const __half* __restrict__ Al,
         const __half* __restrict__ Bh, const __half* __restrict__ Bl,
         float* __restrict__ Y, __half* __restrict__ Hh, __half* __restrict__ Hl)
{
    const int e    = blockIdx.z;
    const int cnt  = g_count[e];
    const int row0 = blockIdx.y * 128;
    if (row0 >= cnt) return;
    const int col0 = blockIdx.x * 128;

    extern __shared__ char smem[];
    const uint32_t sb = smem_u32(smem);

    const int tid  = threadIdx.x;
    const int wid  = tid >> 5;
    const int lane = tid & 31;
    const int warp_m = wid & 3;          // 4 warps over M (32 rows each)
    const int warp_n = wid >> 2;         // 2 warps over N (64 cols each)

    // --- cp.async mapping: thread covers 16B chunk (tid&7) of rows (tid>>3)+i*32
    const int crow = tid >> 3;           // 0..31
    const int ckb  = (tid & 7) * 16;     // byte col within 128B row
    const int chalf = (tid & 7) * 8;     // half offset

    size_t aoff[4]; int avalid[4];
    size_t boff[4];
    uint32_t dsto[4];
#pragma unroll
    for (int i = 0; i < 4; i++) {
        int r = crow + i * 32;
        int gr = row0 + r;
        if (GATHER) {
            avalid[i] = (gr < cnt) ? 16 : 0;
            aoff[i] = (gr < cnt) ? (size_t)g_tok[e * CAP + gr] * KD : 0;
        } else {
            avalid[i] = 16;
            aoff[i] = (size_t)(e * CAP + gr) * KD;
        }
        boff[i] = ((size_t)e * NTOT + col0 + r) * (size_t)KD;
        dsto[i] = (uint32_t)(r * 128 + (ckb ^ ((r & 7) << 4)));   // SW128
    }

    constexpr int CHUNKS = KD / 64;
    constexpr int ITERS  = 3 * CHUNKS;

    auto issue = [&](int it) {
        const int stage = it % 3;
        const int pass  = it / CHUNKS;
        const int c     = it - pass * CHUNKS;
        const __half* Ap = (pass == 1) ? Al : Ah;
        const __half* Bp = (pass == 2) ? Bl : Bh;
        const uint32_t sA = sb + stage * STAGE_BYTES;
        const uint32_t sB = sA + 16384;
        const size_t kofs = (size_t)c * 64 + chalf;
#pragma unroll
        for (int i = 0; i < 4; i++)
            cp_async16(sA + dsto[i], Ap + aoff[i] + kofs, avalid[i]);
#pragma unroll
        for (int i = 0; i < 4; i++)
            cp_async16(sB + dsto[i], Bp + boff[i] + kofs, 16);
        CP_COMMIT();
    };

    float acc[2][8][4];
#pragma unroll
    for (int t = 0; t < 2; t++)
#pragma unroll
        for (int n = 0; n < 8; n++)
#pragma unroll
            for (int q = 0; q < 4; q++) acc[t][n][q] = 0.0f;

    issue(0);
    issue(1);

    // ldmatrix per-lane row/byte precomputation
    const int g  = lane >> 3;
    const int rl = lane & 7;
    const int a_row  = warp_m * 32 + (g & 1) * 8 + rl;       // + t*16
    const int a_byte = (g >> 1) * 16;                        // + kb
    const int b_row  = warp_n * 64 + (g & 2) * 4 + rl;       // + q*16
    const int b_byte = (g & 1) * 16;                         // + kb

#pragma unroll 1
    for (int it = 0; it < ITERS; it++) {
        const int stage = it % 3;
        CP_WAIT1();
        __syncthreads();
        if (it + 2 < ITERS) issue(it + 2);

        const uint32_t sA = sb + stage * STAGE_BYTES;
        const uint32_t sB = sA + 16384;

#pragma unroll
        for (int ks = 0; ks < 4; ks++) {
            const int kb = ks * 32;
            uint32_t af[2][4];
#pragma unroll
            for (int t = 0; t < 2; t++) {
                int row = a_row + t * 16;
                uint32_t addr = sA + row * 128 + ((a_byte + kb) ^ ((row & 7) << 4));
                ldm_x4(addr, af[t]);
            }
            uint32_t bf[8][2];
#pragma unroll
            for (int q = 0; q < 4; q++) {
                int row = b_row + q * 16;
                uint32_t addr = sB + row * 128 + ((b_byte + kb) ^ ((row & 7) << 4));
                uint32_t r4[4];
                ldm_x4(addr, r4);
                bf[2 * q][0] = r4[0]; bf[2 * q][1] = r4[1];
                bf[2 * q + 1][0] = r4[2]; bf[2 * q + 1][1] = r4[3];
            }
#pragma unroll
            for (int t = 0; t < 2; t++)
#pragma unroll
                for (int n = 0; n < 8; n++)
                    mma16816(acc[t][n], af[t], bf[n]);
        }
        __syncthreads();
    }

    // ------------------------------ epilogue ------------------------------
    const int qr = lane >> 2;   // 0..7
    const int qc = lane & 3;    // 0..3

#pragma unroll
    for (int t = 0; t < 2; t++) {
        int r_lo = row0 + warp_m * 32 + t * 16 + qr;
        int r_hi = r_lo + 8;
#pragma unroll
        for (int n = 0; n < 8; n++) {
            if (FUSE) {
                int p = (col0 >> 1) + warp_n * 32 + n * 4 + qc;  // h column
                if (r_lo < cnt) {
                    float gg = acc[t][n][0], uu = acc[t][n][1];
                    float hv = gg / (1.0f + expf(-gg)) * uu;
                    __half hi = __float2half_rn(hv);
                    size_t o = ((size_t)e * CAP + r_lo) * I_ + p;
                    Hh[o] = hi;
                    Hl[o] = __float2half_rn(hv - __half2float(hi));
                }
                if (r_hi < cnt) {
                    float gg = acc[t][n][2], uu = acc[t][n][3];
                    float hv = gg / (1.0f + expf(-gg)) * uu;
                    __half hi = __float2half_rn(hv);
                    size_t o = ((size_t)e * CAP + r_hi) * I_ + p;
                    Hh[o] = hi;
                    Hl[o] = __float2half_rn(hv - __half2float(hi));
                }
            } else {
                int col = col0 + warp_n * 64 + n * 8 + 2 * qc;
                if (r_lo < cnt)
                    *(float2*)&Y[((size_t)e * CAP + r_lo) * NTOT + col] =
                        make_float2(acc[t][n][0], acc[t][n][1]);
                if (r_hi < cnt)
                    *(float2*)&Y[((size_t)e * CAP + r_hi) * NTOT + col] =
                        make_float2(acc[t][n][2], acc[t][n][3]);
            }
        }
    }
}

// ---------------------------------------------------------------------------
// launch
// ---------------------------------------------------------------------------
extern "C" void kernel_launch(void* const* d_in, const int* in_sizes, int n_in,
                              void* d_out, int out_size)
{
    const float* x      = (const float*)d_in[0];
    const float* logits = (const float*)d_in[1];
    const float* w13    = (const float*)d_in[2];
    const float* w2     = (const float*)d_in[3];
    float* out = (float*)d_out;

    __half *w13h, *w13l, *w2h, *w2l, *xh, *xl, *hh, *hl;
    float* y;
    cudaGetSymbolAddress((void**)&w13h, g_w13h);
    cudaGetSymbolAddress((void**)&w13l, g_w13l);
    cudaGetSymbolAddress((void**)&w2h,  g_w2h);
    cudaGetSymbolAddress((void**)&w2l,  g_w2l);
    cudaGetSymbolAddress((void**)&xh,   g_xh);
    cudaGetSymbolAddress((void**)&xl,   g_xl);
    cudaGetSymbolAddress((void**)&hh,   g_hh);
    cudaGetSymbolAddress((void**)&hl,   g_hl);
    cudaGetSymbolAddress((void**)&y,    g_y);

    cudaFuncSetAttribute(moe_gemm<H_, 2 * I_, true,  true >,
                         cudaFuncAttributeMaxDynamicSharedMemorySize, SMEM_BYTES);
    cudaFuncSetAttribute(moe_gemm<I_, H_,     false, false>,
                         cudaFuncAttributeMaxDynamicSharedMemorySize, SMEM_BYTES);

    init_kernel  <<<1, 32>>>();
    router_kernel<<<T_ / 256, 256>>>(logits);

    split_kernel    <<<(T_ * H_ / 4 + 255) / 256, 256>>>(x, xh, xl, (size_t)T_ * H_ / 4);
    split_w13_kernel<<<((size_t)E_ * 2 * I_ * H_ / 4 + 255) / 256, 256>>>(w13, w13h, w13l);
    split_kernel    <<<((size_t)E_ * H_ * I_ / 4 + 255) / 256, 256>>>(w2, w2h, w2l,
                                                                      (size_t)E_ * H_ * I_ / 4);

    // GEMM1 (+ fused silu*up, hi/lo split output): N = 2I = 4096 (gate/up interleaved), K = H
    moe_gemm<H_, 2 * I_, true, true>
        <<<dim3(2 * I_ / 128, CAP / 128, E_), 256, SMEM_BYTES>>>(
            xh, xl, w13h, w13l, nullptr, hh, hl);

    // GEMM2: y = h @ w2^T : N = H = 1024, K = I
    moe_gemm<I_, H_, false, false>
        <<<dim3(H_ / 128, CAP / 128, E_), 256, SMEM_BYTES>>>(
            hh, hl, w2h, w2l, y, nullptr, nullptr);

    combine_kernel<<<T_, 256>>>(out);
}

// round 4
// speedup vs baseline: 4.2525x; 1.4428x over previous
#include <cuda_runtime.h>
#include <cuda_fp16.h>
#include <math.h>
#include <stdint.h>

// Problem constants
constexpr int T_  = 4096;
constexpr int E_  = 8;
constexpr int H_  = 1024;
constexpr int I_  = 2048;
constexpr int CAP = 4096;

// ---------------------------------------------------------------------------
// Scratch (device globals)
// ---------------------------------------------------------------------------
__device__ int   g_count[E_];
__device__ int   g_tok[E_ * CAP];
__device__ int   g_slot[T_ * 2];
__device__ float g_wt[T_ * 2];

__device__ __half g_w13h[(size_t)E_ * 2 * I_ * H_];  // permuted rows: 2j=gate_j, 2j+1=up_j
__device__ __half g_w2h [(size_t)E_ * H_ * I_];
__device__ __half g_xh  [(size_t)T_ * H_];
__device__ __half g_xl  [(size_t)T_ * H_];
__device__ __half g_hh  [(size_t)E_ * CAP * I_];
__device__ __half g_hl  [(size_t)E_ * CAP * I_];
__device__ float  g_y   [(size_t)E_ * CAP * H_];

// ---------------------------------------------------------------------------
// helpers
// ---------------------------------------------------------------------------
__device__ __forceinline__ uint32_t smem_u32(const void* p) {
    uint32_t a;
    asm("{ .reg .u64 t; cvta.to.shared.u64 t, %1; cvt.u32.u64 %0, t; }" : "=r"(a) : "l"(p));
    return a;
}
__device__ __forceinline__ void cp_async16(uint32_t dst, const void* src, int src_bytes) {
    asm volatile("cp.async.cg.shared.global [%0], [%1], 16, %2;"
                 :: "r"(dst), "l"(src), "r"(src_bytes));
}
#define CP_COMMIT() asm volatile("cp.async.commit_group;" ::: "memory")
#define CP_WAIT1()  asm volatile("cp.async.wait_group 1;" ::: "memory")

__device__ __forceinline__ void ldm_x4(uint32_t addr, uint32_t* r) {
    asm volatile("ldmatrix.sync.aligned.m8n8.x4.shared.b16 {%0,%1,%2,%3}, [%4];"
                 : "=r"(r[0]), "=r"(r[1]), "=r"(r[2]), "=r"(r[3]) : "r"(addr));
}
__device__ __forceinline__ void mma16816(float* c, const uint32_t* a, const uint32_t* b) {
    asm volatile("mma.sync.aligned.m16n8k16.row.col.f32.f16.f16.f32 "
                 "{%0,%1,%2,%3}, {%4,%5,%6,%7}, {%8,%9}, {%0,%1,%2,%3};"
                 : "+f"(c[0]), "+f"(c[1]), "+f"(c[2]), "+f"(c[3])
                 : "r"(a[0]), "r"(a[1]), "r"(a[2]), "r"(a[3]), "r"(b[0]), "r"(b[1]));
}

// SMEM: 3 stages x (A 16KB + B 16KB); K-chunk = 64 halves = 128B rows, SW128 swizzle
static constexpr int STAGE_BYTES = 32768;
static constexpr uint32_t SMEM_BYTES = 3 * STAGE_BYTES;   // 98304

// ---------------------------------------------------------------------------
// router / init / combine
// ---------------------------------------------------------------------------
__global__ void init_kernel() { if (threadIdx.x < E_) g_count[threadIdx.x] = 0; }

__global__ void router_kernel(const float* __restrict__ logits) {
    int t = blockIdx.x * blockDim.x + threadIdx.x;
    if (t >= T_) return;
    float l[E_];
#pragma unroll
    for (int e = 0; e < E_; e++) l[e] = logits[t * E_ + e];
    int b0 = 0; float m0 = l[0];
#pragma unroll
    for (int e = 1; e < E_; e++) if (l[e] > m0) { m0 = l[e]; b0 = e; }
    int b1 = -1; float m1 = -3.0e38f;
#pragma unroll
    for (int e = 0; e < E_; e++) if (e != b0 && l[e] > m1) { m1 = l[e]; b1 = e; }
    float w0 = 1.0f / (1.0f + expf(m1 - m0));
    float w1 = 1.0f - w0;
    int p0 = atomicAdd(&g_count[b0], 1);
    g_tok[b0 * CAP + p0] = t;  g_slot[2 * t + 0] = b0 * CAP + p0;  g_wt[2 * t + 0] = w0;
    int p1 = atomicAdd(&g_count[b1], 1);
    g_tok[b1 * CAP + p1] = t;  g_slot[2 * t + 1] = b1 * CAP + p1;  g_wt[2 * t + 1] = w1;
}

__global__ void combine_kernel(float* __restrict__ out) {
    int t = blockIdx.x;
    int   s0 = g_slot[2 * t + 0], s1 = g_slot[2 * t + 1];
    float w0 = g_wt [2 * t + 0], w1 = g_wt [2 * t + 1];
    const float* y0 = g_y + (size_t)s0 * H_;
    const float* y1 = g_y + (size_t)s1 * H_;
    float* o = out + (size_t)t * H_;
    for (int j = threadIdx.x; j < H_; j += blockDim.x)
        o[j] = w0 * y0[j] + w1 * y1[j];
}

// ---------------------------------------------------------------------------
// conversion kernels
// ---------------------------------------------------------------------------
// fp32 -> fp16 hi/lo split (x only)
__global__ void split_kernel(const float* __restrict__ s, __half* __restrict__ h,
                             __half* __restrict__ l, size_t n4) {
    size_t i = blockIdx.x * (size_t)blockDim.x + threadIdx.x;
    if (i >= n4) return;
    float4 v = ((const float4*)s)[i];
    __half h0 = __float2half_rn(v.x), h1 = __float2half_rn(v.y),
           h2 = __float2half_rn(v.z), h3 = __float2half_rn(v.w);
    ((__half2*)h)[2 * i]     = __halves2half2(h0, h1);
    ((__half2*)h)[2 * i + 1] = __halves2half2(h2, h3);
    ((__half2*)l)[2 * i]     = __halves2half2(__float2half_rn(v.x - __half2float(h0)),
                                              __float2half_rn(v.y - __half2float(h1)));
    ((__half2*)l)[2 * i + 1] = __halves2half2(__float2half_rn(v.z - __half2float(h2)),
                                              __float2half_rn(v.w - __half2float(h3)));
}

// fp32 -> fp16 (hi only), linear (w2)
__global__ void convert_kernel(const float* __restrict__ s, __half* __restrict__ h, size_t n4) {
    size_t i = blockIdx.x * (size_t)blockDim.x + threadIdx.x;
    if (i >= n4) return;
    float4 v = ((const float4*)s)[i];
    ((__half2*)h)[2 * i]     = __halves2half2(__float2half_rn(v.x), __float2half_rn(v.y));
    ((__half2*)h)[2 * i + 1] = __halves2half2(__float2half_rn(v.z), __float2half_rn(v.w));
}

// w13: fp32 -> fp16 (hi only) + row interleave: out row 2j=gate_j, 2j+1=up_j
__global__ void split_w13_kernel(const float* __restrict__ s, __half* __restrict__ h) {
    size_t i = blockIdx.x * (size_t)blockDim.x + threadIdx.x;  // float4 index
    size_t total = (size_t)E_ * 2 * I_ * H_ / 4;
    if (i >= total) return;
    float4 v = ((const float4*)s)[i];
    size_t hp  = i % (H_ / 4);
    size_t row = i / (H_ / 4);
    size_t e  = row / (2 * I_);
    size_t jj = row % (2 * I_);
    size_t r  = (jj < (size_t)I_) ? (2 * jj) : (2 * (jj - I_) + 1);
    size_t o  = (e * (size_t)(2 * I_) + r) * (H_ / 4) + hp;
    ((__half2*)h)[2 * o]     = __halves2half2(__float2half_rn(v.x), __float2half_rn(v.y));
    ((__half2*)h)[2 * o + 1] = __halves2half2(__float2half_rn(v.z), __float2half_rn(v.w));
}

// ---------------------------------------------------------------------------
// HMMA GEMM: per expert z, C[128x128 tile] = A[128,K] @ B[N,K]^T
// 2-term error compensation: Ah*Bh + Al*Bh (fp32 accum in registers).
// GATHER: A rows via g_tok.  FUSE: epilogue silu(g)*u -> h hi/lo via SMEM
// staging (gate/up interleaved in B columns so each accum pair is (g,u)).
// ---------------------------------------------------------------------------
template <int KD, int NTOT, bool GATHER, bool FUSE>
__global__ void __launch_bounds__(256)
moe_gemm(const __half* __restrict__ Ah, const __half* __restrict__ Al,
         const __half* __restrict__ Bh,
         float* __restrict__ Y, __half* __restrict__ Hh, __half* __restrict__ Hl)
{
    const int e    = blockIdx.z;
    const int cnt  = g_count[e];
    const int row0 = blockIdx.y * 128;
    if (row0 >= cnt) return;
    const int col0 = blockIdx.x * 128;

    extern __shared__ char smem[];
    const uint32_t sb = smem_u32(smem);

    const int tid  = threadIdx.x;
    const int wid  = tid >> 5;
    const int lane = tid & 31;
    const int warp_m = wid & 3;          // 4 warps over M (32 rows each)
    const int warp_n = wid >> 2;         // 2 warps over N (64 cols each)

    // --- cp.async mapping: thread covers 16B chunk (tid&7) of rows (tid>>3)+i*32
    const int crow = tid >> 3;           // 0..31
    const int ckb  = (tid & 7) * 16;     // byte col within 128B row
    const int chalf = (tid & 7) * 8;     // half offset

    size_t aoff[4]; int avalid[4];
    size_t boff[4];
    uint32_t dsto[4];
#pragma unroll
    for (int i = 0; i < 4; i++) {
        int r = crow + i * 32;
        int gr = row0 + r;
        if (GATHER) {
            avalid[i] = (gr < cnt) ? 16 : 0;
            aoff[i] = (gr < cnt) ? (size_t)g_tok[e * CAP + gr] * KD : 0;
        } else {
            avalid[i] = 16;
            aoff[i] = (size_t)(e * CAP + gr) * KD;
        }
        boff[i] = ((size_t)e * NTOT + col0 + r) * (size_t)KD;
        dsto[i] = (uint32_t)(r * 128 + (ckb ^ ((r & 7) << 4)));   // SW128
    }

    constexpr int CHUNKS = KD / 64;
    constexpr int ITERS  = 2 * CHUNKS;    // pass0: Ah*Bh, pass1: Al*Bh

    auto issue = [&](int it) {
        const int stage = it % 3;
        const int pass  = it / CHUNKS;
        const int c     = it - pass * CHUNKS;
        const __half* Ap = pass ? Al : Ah;
        const uint32_t sA = sb + stage * STAGE_BYTES;
        const uint32_t sB = sA + 16384;
        const size_t kofs = (size_t)c * 64 + chalf;
#pragma unroll
        for (int i = 0; i < 4; i++)
            cp_async16(sA + dsto[i], Ap + aoff[i] + kofs, avalid[i]);
#pragma unroll
        for (int i = 0; i < 4; i++)
            cp_async16(sB + dsto[i], Bh + boff[i] + kofs, 16);
        CP_COMMIT();
    };

    float acc[2][8][4];
#pragma unroll
    for (int t = 0; t < 2; t++)
#pragma unroll
        for (int n = 0; n < 8; n++)
#pragma unroll
            for (int q = 0; q < 4; q++) acc[t][n][q] = 0.0f;

    issue(0);
    issue(1);

    // ldmatrix per-lane row/byte precomputation
    const int g  = lane >> 3;
    const int rl = lane & 7;
    const int a_row  = warp_m * 32 + (g & 1) * 8 + rl;       // + t*16
    const int a_byte = (g >> 1) * 16;                        // + kb
    const int b_row  = warp_n * 64 + (g & 2) * 4 + rl;       // + q*16
    const int b_byte = (g & 1) * 16;                         // + kb

#pragma unroll 1
    for (int it = 0; it < ITERS; it++) {
        const int stage = it % 3;
        CP_WAIT1();
        __syncthreads();
        if (it + 2 < ITERS) issue(it + 2);

        const uint32_t sA = sb + stage * STAGE_BYTES;
        const uint32_t sB = sA + 16384;

#pragma unroll
        for (int ks = 0; ks < 4; ks++) {
            const int kb = ks * 32;
            uint32_t af[2][4];
#pragma unroll
            for (int t = 0; t < 2; t++) {
                int row = a_row + t * 16;
                uint32_t addr = sA + row * 128 + ((a_byte + kb) ^ ((row & 7) << 4));
                ldm_x4(addr, af[t]);
            }
            uint32_t bf[8][2];
#pragma unroll
            for (int q = 0; q < 4; q++) {
                int row = b_row + q * 16;
                uint32_t addr = sB + row * 128 + ((b_byte + kb) ^ ((row & 7) << 4));
                uint32_t r4[4];
                ldm_x4(addr, r4);
                bf[2 * q][0] = r4[0]; bf[2 * q][1] = r4[1];
                bf[2 * q + 1][0] = r4[2]; bf[2 * q + 1][1] = r4[3];
            }
#pragma unroll
            for (int t = 0; t < 2; t++)
#pragma unroll
                for (int n = 0; n < 8; n++)
                    mma16816(acc[t][n], af[t], bf[n]);
        }
        __syncthreads();
    }

    // ------------------------------ epilogue ------------------------------
    const int qr = lane >> 2;   // 0..7
    const int qc = lane & 3;    // 0..3

    if (FUSE) {
        // Stage silu(g)*u hi/lo halves in this warp's private 4KB SMEM region
        // (stages no longer in use), then write coalesced 16B stores.
        char* wreg = smem + wid * 4096;   // [0,2048)=hi, [2048,4096)=lo
#pragma unroll
        for (int t = 0; t < 2; t++) {
#pragma unroll
            for (int n = 0; n < 8; n++) {
                int cl = (n * 4 + qc) * 2;          // byte col within 64B row
                {   // rows t*16+qr (c0,c1)
                    float gg = acc[t][n][0], uu = acc[t][n][1];
                    float hv = gg / (1.0f + expf(-gg)) * uu;
                    __half hi = __float2half_rn(hv);
                    int rb = (t * 16 + qr) * 64;
                    *(__half*)(wreg + rb + cl)        = hi;
                    *(__half*)(wreg + 2048 + rb + cl) = __float2half_rn(hv - __half2float(hi));
                }
                {   // rows t*16+qr+8 (c2,c3)
                    float gg = acc[t][n][2], uu = acc[t][n][3];
                    float hv = gg / (1.0f + expf(-gg)) * uu;
                    __half hi = __float2half_rn(hv);
                    int rb = (t * 16 + qr + 8) * 64;
                    *(__half*)(wreg + rb + cl)        = hi;
                    *(__half*)(wreg + 2048 + rb + cl) = __float2half_rn(hv - __half2float(hi));
                }
            }
        }
        __syncwarp();
        const size_t pbase = (size_t)(col0 >> 1) + warp_n * 32;
#pragma unroll
        for (int p = 0; p < 4; p++) {
            int row_local = p * 8 + (lane >> 2);
            int c16 = lane & 3;
            int r = row0 + warp_m * 32 + row_local;
            if (r < cnt) {
                uint4 vh = *(uint4*)(wreg + row_local * 64 + c16 * 16);
                uint4 vl = *(uint4*)(wreg + 2048 + row_local * 64 + c16 * 16);
                size_t o = ((size_t)e * CAP + r) * I_ + pbase + c16 * 8;
                *(uint4*)(Hh + o) = vh;
                *(uint4*)(Hl + o) = vl;
            }
        }
    } else {
#pragma unroll
        for (int t = 0; t < 2; t++) {
            int r_lo = row0 + warp_m * 32 + t * 16 + qr;
            int r_hi = r_lo + 8;
#pragma unroll
            for (int n = 0; n < 8; n++) {
                int col = col0 + warp_n * 64 + n * 8 + 2 * qc;
                if (r_lo < cnt)
                    *(float2*)&Y[((size_t)e * CAP + r_lo) * NTOT + col] =
                        make_float2(acc[t][n][0], acc[t][n][1]);
                if (r_hi < cnt)
                    *(float2*)&Y[((size_t)e * CAP + r_hi) * NTOT + col] =
                        make_float2(acc[t][n][2], acc[t][n][3]);
            }
        }
    }
}

// ---------------------------------------------------------------------------
// launch
// ---------------------------------------------------------------------------
extern "C" void kernel_launch(void* const* d_in, const int* in_sizes, int n_in,
                              void* d_out, int out_size)
{
    const float* x      = (const float*)d_in[0];
    const float* logits = (const float*)d_in[1];
    const float* w13    = (const float*)d_in[2];
    const float* w2     = (const float*)d_in[3];
    float* out = (float*)d_out;

    __half *w13h, *w2h, *xh, *xl, *hh, *hl;
    float* y;
    cudaGetSymbolAddress((void**)&w13h, g_w13h);
    cudaGetSymbolAddress((void**)&w2h,  g_w2h);
    cudaGetSymbolAddress((void**)&xh,   g_xh);
    cudaGetSymbolAddress((void**)&xl,   g_xl);
    cudaGetSymbolAddress((void**)&hh,   g_hh);
    cudaGetSymbolAddress((void**)&hl,   g_hl);
    cudaGetSymbolAddress((void**)&y,    g_y);

    cudaFuncSetAttribute(moe_gemm<H_, 2 * I_, true,  true >,
                         cudaFuncAttributeMaxDynamicSharedMemorySize, SMEM_BYTES);
    cudaFuncSetAttribute(moe_gemm<I_, H_,     false, false>,
                         cudaFuncAttributeMaxDynamicSharedMemorySize, SMEM_BYTES);

    init_kernel  <<<1, 32>>>();
    router_kernel<<<T_ / 256, 256>>>(logits);

    split_kernel    <<<(T_ * H_ / 4 + 255) / 256, 256>>>(x, xh, xl, (size_t)T_ * H_ / 4);
    split_w13_kernel<<<((size_t)E_ * 2 * I_ * H_ / 4 + 255) / 256, 256>>>(w13, w13h);
    convert_kernel  <<<((size_t)E_ * H_ * I_ / 4 + 255) / 256, 256>>>(w2, w2h,
                                                                      (size_t)E_ * H_ * I_ / 4);

    // GEMM1 (+ fused silu*up, hi/lo split output): N = 2I = 4096 (gate/up interleaved), K = H
    moe_gemm<H_, 2 * I_, true, true>
        <<<dim3(2 * I_ / 128, CAP / 128, E_), 256, SMEM_BYTES>>>(
            xh, xl, w13h, nullptr, hh, hl);

    // GEMM2: y = h @ w2^T : N = H = 1024, K = I
    moe_gemm<I_, H_, false, false>
        <<<dim3(H_ / 128, CAP / 128, E_), 256, SMEM_BYTES>>>(
            hh, hl, w2h, y, nullptr, nullptr);

    combine_kernel<<<T_, 256>>>(out);
}

// round 5
// speedup vs baseline: 4.7037x; 1.1061x over previous
#include <cuda_runtime.h>
#include <cuda_fp16.h>
#include <math.h>
#include <stdint.h>

// Problem constants
constexpr int T_  = 4096;
constexpr int E_  = 8;
constexpr int H_  = 1024;
constexpr int I_  = 2048;
constexpr int CAP = 4096;

// ---------------------------------------------------------------------------
// Scratch (device globals)
// ---------------------------------------------------------------------------
__device__ int   g_count[E_];
__device__ int   g_tok[E_ * CAP];
__device__ int   g_slot[T_ * 2];
__device__ float g_wt[T_ * 2];

__device__ __half g_w13h[(size_t)E_ * 2 * I_ * H_];  // permuted rows: 2j=gate_j, 2j+1=up_j
__device__ __half g_w2h [(size_t)E_ * H_ * I_];
__device__ __half g_xh  [(size_t)T_ * H_];
__device__ __half g_xl  [(size_t)T_ * H_];
__device__ __half g_hh  [(size_t)E_ * CAP * I_];
__device__ __half g_hl  [(size_t)E_ * CAP * I_];
__device__ float  g_y   [(size_t)E_ * CAP * H_];

// ---------------------------------------------------------------------------
// helpers
// ---------------------------------------------------------------------------
__device__ __forceinline__ uint32_t smem_u32(const void* p) {
    uint32_t a;
    asm("{ .reg .u64 t; cvta.to.shared.u64 t, %1; cvt.u32.u64 %0, t; }" : "=r"(a) : "l"(p));
    return a;
}
__device__ __forceinline__ void cp_async16(uint32_t dst, const void* src, int src_bytes) {
    asm volatile("cp.async.cg.shared.global [%0], [%1], 16, %2;"
                 :: "r"(dst), "l"(src), "r"(src_bytes));
}
#define CP_COMMIT() asm volatile("cp.async.commit_group;" ::: "memory")
#define CP_WAIT1()  asm volatile("cp.async.wait_group 1;" ::: "memory")

__device__ __forceinline__ void ldm_x4(uint32_t addr, uint32_t* r) {
    asm volatile("ldmatrix.sync.aligned.m8n8.x4.shared.b16 {%0,%1,%2,%3}, [%4];"
                 : "=r"(r[0]), "=r"(r[1]), "=r"(r[2]), "=r"(r[3]) : "r"(addr));
}
__device__ __forceinline__ void mma16816(float* c, const uint32_t* a, const uint32_t* b) {
    asm volatile("mma.sync.aligned.m16n8k16.row.col.f32.f16.f16.f32 "
                 "{%0,%1,%2,%3}, {%4,%5,%6,%7}, {%8,%9}, {%0,%1,%2,%3};"
                 : "+f"(c[0]), "+f"(c[1]), "+f"(c[2]), "+f"(c[3])
                 : "r"(a[0]), "r"(a[1]), "r"(a[2]), "r"(a[3]), "r"(b[0]), "r"(b[1]));
}

// SMEM: 2 stages x (Ah 16KB + Al 16KB + B 16KB); K-chunk = 64 halves (128B rows, SW128)
static constexpr int STAGE_BYTES = 49152;
static constexpr uint32_t SMEM_BYTES = 2 * STAGE_BYTES;   // 98304

// ---------------------------------------------------------------------------
// router / init / combine
// ---------------------------------------------------------------------------
__global__ void init_kernel() { if (threadIdx.x < E_) g_count[threadIdx.x] = 0; }

__global__ void router_kernel(const float* __restrict__ logits) {
    int t = blockIdx.x * blockDim.x + threadIdx.x;
    if (t >= T_) return;
    float l[E_];
#pragma unroll
    for (int e = 0; e < E_; e++) l[e] = logits[t * E_ + e];
    int b0 = 0; float m0 = l[0];
#pragma unroll
    for (int e = 1; e < E_; e++) if (l[e] > m0) { m0 = l[e]; b0 = e; }
    int b1 = -1; float m1 = -3.0e38f;
#pragma unroll
    for (int e = 0; e < E_; e++) if (e != b0 && l[e] > m1) { m1 = l[e]; b1 = e; }
    float w0 = 1.0f / (1.0f + expf(m1 - m0));
    float w1 = 1.0f - w0;
    int p0 = atomicAdd(&g_count[b0], 1);
    g_tok[b0 * CAP + p0] = t;  g_slot[2 * t + 0] = b0 * CAP + p0;  g_wt[2 * t + 0] = w0;
    int p1 = atomicAdd(&g_count[b1], 1);
    g_tok[b1 * CAP + p1] = t;  g_slot[2 * t + 1] = b1 * CAP + p1;  g_wt[2 * t + 1] = w1;
}

__global__ void combine_kernel(float* __restrict__ out) {
    int t = blockIdx.x;
    int   s0 = g_slot[2 * t + 0], s1 = g_slot[2 * t + 1];
    float w0 = g_wt [2 * t + 0], w1 = g_wt [2 * t + 1];
    const float* y0 = g_y + (size_t)s0 * H_;
    const float* y1 = g_y + (size_t)s1 * H_;
    float* o = out + (size_t)t * H_;
    for (int j = threadIdx.x; j < H_; j += blockDim.x)
        o[j] = w0 * y0[j] + w1 * y1[j];
}

// ---------------------------------------------------------------------------
// conversion kernels
// ---------------------------------------------------------------------------
// fp32 -> fp16 hi/lo split (x only)
__global__ void split_kernel(const float* __restrict__ s, __half* __restrict__ h,
                             __half* __restrict__ l, size_t n4) {
    size_t i = blockIdx.x * (size_t)blockDim.x + threadIdx.x;
    if (i >= n4) return;
    float4 v = ((const float4*)s)[i];
    __half h0 = __float2half_rn(v.x), h1 = __float2half_rn(v.y),
           h2 = __float2half_rn(v.z), h3 = __float2half_rn(v.w);
    ((__half2*)h)[2 * i]     = __halves2half2(h0, h1);
    ((__half2*)h)[2 * i + 1] = __halves2half2(h2, h3);
    ((__half2*)l)[2 * i]     = __halves2half2(__float2half_rn(v.x - __half2float(h0)),
                                              __float2half_rn(v.y - __half2float(h1)));
    ((__half2*)l)[2 * i + 1] = __halves2half2(__float2half_rn(v.z - __half2float(h2)),
                                              __float2half_rn(v.w - __half2float(h3)));
}

// fp32 -> fp16 (hi only), linear (w2)
__global__ void convert_kernel(const float* __restrict__ s, __half* __restrict__ h, size_t n4) {
    size_t i = blockIdx.x * (size_t)blockDim.x + threadIdx.x;
    if (i >= n4) return;
    float4 v = ((const float4*)s)[i];
    ((__half2*)h)[2 * i]     = __halves2half2(__float2half_rn(v.x), __float2half_rn(v.y));
    ((__half2*)h)[2 * i + 1] = __halves2half2(__float2half_rn(v.z), __float2half_rn(v.w));
}

// w13: fp32 -> fp16 (hi only) + row interleave: out row 2j=gate_j, 2j+1=up_j
__global__ void split_w13_kernel(const float* __restrict__ s, __half* __restrict__ h) {
    size_t i = blockIdx.x * (size_t)blockDim.x + threadIdx.x;  // float4 index
    size_t total = (size_t)E_ * 2 * I_ * H_ / 4;
    if (i >= total) return;
    float4 v = ((const float4*)s)[i];
    size_t hp  = i % (H_ / 4);
    size_t row = i / (H_ / 4);
    size_t e  = row / (2 * I_);
    size_t jj = row % (2 * I_);
    size_t r  = (jj < (size_t)I_) ? (2 * jj) : (2 * (jj - I_) + 1);
    size_t o  = (e * (size_t)(2 * I_) + r) * (H_ / 4) + hp;
    ((__half2*)h)[2 * o]     = __halves2half2(__float2half_rn(v.x), __float2half_rn(v.y));
    ((__half2*)h)[2 * o + 1] = __halves2half2(__float2half_rn(v.z), __float2half_rn(v.w));
}

// ---------------------------------------------------------------------------
// HMMA GEMM: per expert z, C[128x128 tile] = A[128,K] @ B[N,K]^T
// Fused dual-pass: per k-chunk, stage Ah+Al+B and issue (Ah*Bh + Al*Bh)
// against the same B fragments; fp32 accum in registers.
// GATHER: A rows via g_tok.  FUSE: epilogue silu(g)*u -> h hi/lo via SMEM
// staging (gate/up interleaved in B columns so each accum pair is (g,u)).
// ---------------------------------------------------------------------------
template <int KD, int NTOT, bool GATHER, bool FUSE>
__global__ void __launch_bounds__(256, 2)
moe_gemm(const __half* __restrict__ Ah, const __half* __restrict__ Al,
         const __half* __restrict__ Bh,
         float* __restrict__ Y, __half* __restrict__ Hh, __half* __restrict__ Hl)
{
    const int e    = blockIdx.z;
    const int cnt  = g_count[e];
    const int row0 = blockIdx.y * 128;
    if (row0 >= cnt) return;
    const int col0 = blockIdx.x * 128;

    extern __shared__ char smem[];
    const uint32_t sb = smem_u32(smem);

    const int tid  = threadIdx.x;
    const int wid  = tid >> 5;
    const int lane = tid & 31;
    const int warp_m = wid & 3;          // 4 warps over M (32 rows each)
    const int warp_n = wid >> 2;         // 2 warps over N (64 cols each)

    // --- cp.async mapping: thread covers 16B chunk (tid&7) of rows (tid>>3)+i*32
    const int crow = tid >> 3;           // 0..31
    const int ckb  = (tid & 7) * 16;     // byte col within 128B row
    const int chalf = (tid & 7) * 8;     // half offset

    size_t aoff[4]; int avalid[4];
    size_t boff[4];
    uint32_t dsto[4];
#pragma unroll
    for (int i = 0; i < 4; i++) {
        int r = crow + i * 32;
        int gr = row0 + r;
        if (GATHER) {
            avalid[i] = (gr < cnt) ? 16 : 0;
            aoff[i] = (gr < cnt) ? (size_t)g_tok[e * CAP + gr] * KD : 0;
        } else {
            avalid[i] = 16;
            aoff[i] = (size_t)(e * CAP + gr) * KD;
        }
        boff[i] = ((size_t)e * NTOT + col0 + r) * (size_t)KD;
        dsto[i] = (uint32_t)(r * 128 + (ckb ^ ((r & 7) << 4)));   // SW128
    }

    constexpr int CHUNKS = KD / 64;

    auto issue = [&](int c) {
        const uint32_t sA = sb + (c & 1) * STAGE_BYTES;   // Ah
        const uint32_t sL = sA + 16384;                   // Al
        const uint32_t sB = sA + 32768;                   // B
        const size_t kofs = (size_t)c * 64 + chalf;
#pragma unroll
        for (int i = 0; i < 4; i++)
            cp_async16(sA + dsto[i], Ah + aoff[i] + kofs, avalid[i]);
#pragma unroll
        for (int i = 0; i < 4; i++)
            cp_async16(sL + dsto[i], Al + aoff[i] + kofs, avalid[i]);
#pragma unroll
        for (int i = 0; i < 4; i++)
            cp_async16(sB + dsto[i], Bh + boff[i] + kofs, 16);
        CP_COMMIT();
    };

    float acc[2][8][4];
#pragma unroll
    for (int t = 0; t < 2; t++)
#pragma unroll
        for (int n = 0; n < 8; n++)
#pragma unroll
            for (int q = 0; q < 4; q++) acc[t][n][q] = 0.0f;

    issue(0);

    // ldmatrix per-lane row/byte precomputation
    const int g  = lane >> 3;
    const int rl = lane & 7;
    const int a_row  = warp_m * 32 + (g & 1) * 8 + rl;       // + t*16
    const int a_byte = (g >> 1) * 16;                        // + kb
    const int b_row  = warp_n * 64 + (g & 2) * 4 + rl;       // + q*16
    const int b_byte = (g & 1) * 16;                         // + kb

#pragma unroll 1
    for (int it = 0; it < CHUNKS; it++) {
        if (it + 1 < CHUNKS) issue(it + 1);
        CP_WAIT1();
        __syncthreads();

        const uint32_t sA = sb + (it & 1) * STAGE_BYTES;
        const uint32_t sL = sA + 16384;
        const uint32_t sB = sA + 32768;

#pragma unroll
        for (int ks = 0; ks < 4; ks++) {
            const int kb = ks * 32;
            uint32_t af[2][4], al[2][4];
#pragma unroll
            for (int t = 0; t < 2; t++) {
                int row = a_row + t * 16;
                uint32_t sw = row * 128 + ((a_byte + kb) ^ ((row & 7) << 4));
                ldm_x4(sA + sw, af[t]);
                ldm_x4(sL + sw, al[t]);
            }
            uint32_t bf[8][2];
#pragma unroll
            for (int q = 0; q < 4; q++) {
                int row = b_row + q * 16;
                uint32_t addr = sB + row * 128 + ((b_byte + kb) ^ ((row & 7) << 4));
                uint32_t r4[4];
                ldm_x4(addr, r4);
                bf[2 * q][0] = r4[0]; bf[2 * q][1] = r4[1];
                bf[2 * q + 1][0] = r4[2]; bf[2 * q + 1][1] = r4[3];
            }
#pragma unroll
            for (int t = 0; t < 2; t++)
#pragma unroll
                for (int n = 0; n < 8; n++) {
                    mma16816(acc[t][n], af[t], bf[n]);
                    mma16816(acc[t][n], al[t], bf[n]);
                }
        }
        __syncthreads();
    }

    // ------------------------------ epilogue ------------------------------
    const int qr = lane >> 2;   // 0..7
    const int qc = lane & 3;    // 0..3

    if (FUSE) {
        // Stage silu(g)*u hi/lo halves in this warp's private 4KB SMEM region
        // (stages no longer in use), then write coalesced 16B stores.
        char* wreg = smem + wid * 4096;   // [0,2048)=hi, [2048,4096)=lo
#pragma unroll
        for (int t = 0; t < 2; t++) {
#pragma unroll
            for (int n = 0; n < 8; n++) {
                int cl = (n * 4 + qc) * 2;          // byte col within 64B row
                {   // rows t*16+qr (c0,c1)
                    float gg = acc[t][n][0], uu = acc[t][n][1];
                    float hv = gg / (1.0f + expf(-gg)) * uu;
                    __half hi = __float2half_rn(hv);
                    int rb = (t * 16 + qr) * 64;
                    *(__half*)(wreg + rb + cl)        = hi;
                    *(__half*)(wreg + 2048 + rb + cl) = __float2half_rn(hv - __half2float(hi));
                }
                {   // rows t*16+qr+8 (c2,c3)
                    float gg = acc[t][n][2], uu = acc[t][n][3];
                    float hv = gg / (1.0f + expf(-gg)) * uu;
                    __half hi = __float2half_rn(hv);
                    int rb = (t * 16 + qr + 8) * 64;
                    *(__half*)(wreg + rb + cl)        = hi;
                    *(__half*)(wreg + 2048 + rb + cl) = __float2half_rn(hv - __half2float(hi));
                }
            }
        }
        __syncwarp();
        const size_t pbase = (size_t)(col0 >> 1) + warp_n * 32;
#pragma unroll
        for (int p = 0; p < 4; p++) {
            int row_local = p * 8 + (lane >> 2);
            int c16 = lane & 3;
            int r = row0 + warp_m * 32 + row_local;
            if (r < cnt) {
                uint4 vh = *(uint4*)(wreg + row_local * 64 + c16 * 16);
                uint4 vl = *(uint4*)(wreg + 2048 + row_local * 64 + c16 * 16);
                size_t o = ((size_t)e * CAP + r) * I_ + pbase + c16 * 8;
                *(uint4*)(Hh + o) = vh;
                *(uint4*)(Hl + o) = vl;
            }
        }
    } else {
#pragma unroll
        for (int t = 0; t < 2; t++) {
            int r_lo = row0 + warp_m * 32 + t * 16 + qr;
            int r_hi = r_lo + 8;
#pragma unroll
            for (int n = 0; n < 8; n++) {
                int col = col0 + warp_n * 64 + n * 8 + 2 * qc;
                if (r_lo < cnt)
                    *(float2*)&Y[((size_t)e * CAP + r_lo) * NTOT + col] =
                        make_float2(acc[t][n][0], acc[t][n][1]);
                if (r_hi < cnt)
                    *(float2*)&Y[((size_t)e * CAP + r_hi) * NTOT + col] =
                        make_float2(acc[t][n][2], acc[t][n][3]);
            }
        }
    }
}

// ---------------------------------------------------------------------------
// launch
// ---------------------------------------------------------------------------
extern "C" void kernel_launch(void* const* d_in, const int* in_sizes, int n_in,
                              void* d_out, int out_size)
{
    const float* x      = (const float*)d_in[0];
    const float* logits = (const float*)d_in[1];
    const float* w13    = (const float*)d_in[2];
    const float* w2     = (const float*)d_in[3];
    float* out = (float*)d_out;

    __half *w13h, *w2h, *xh, *xl, *hh, *hl;
    float* y;
    cudaGetSymbolAddress((void**)&w13h, g_w13h);
    cudaGetSymbolAddress((void**)&w2h,  g_w2h);
    cudaGetSymbolAddress((void**)&xh,   g_xh);
    cudaGetSymbolAddress((void**)&xl,   g_xl);
    cudaGetSymbolAddress((void**)&hh,   g_hh);
    cudaGetSymbolAddress((void**)&hl,   g_hl);
    cudaGetSymbolAddress((void**)&y,    g_y);

    cudaFuncSetAttribute(moe_gemm<H_, 2 * I_, true,  true >,
                         cudaFuncAttributeMaxDynamicSharedMemorySize, SMEM_BYTES);
    cudaFuncSetAttribute(moe_gemm<I_, H_,     false, false>,
                         cudaFuncAttributeMaxDynamicSharedMemorySize, SMEM_BYTES);

    init_kernel  <<<1, 32>>>();
    router_kernel<<<T_ / 256, 256>>>(logits);

    split_kernel    <<<(T_ * H_ / 4 + 255) / 256, 256>>>(x, xh, xl, (size_t)T_ * H_ / 4);
    split_w13_kernel<<<((size_t)E_ * 2 * I_ * H_ / 4 + 255) / 256, 256>>>(w13, w13h);
    convert_kernel  <<<((size_t)E_ * H_ * I_ / 4 + 255) / 256, 256>>>(w2, w2h,
                                                                      (size_t)E_ * H_ * I_ / 4);

    // GEMM1 (+ fused silu*up, hi/lo split output): N = 2I = 4096 (gate/up interleaved), K = H
    moe_gemm<H_, 2 * I_, true, true>
        <<<dim3(2 * I_ / 128, CAP / 128, E_), 256, SMEM_BYTES>>>(
            xh, xl, w13h, nullptr, hh, hl);

    // GEMM2: y = h @ w2^T : N = H = 1024, K = I
    moe_gemm<I_, H_, false, false>
        <<<dim3(H_ / 128, CAP / 128, E_), 256, SMEM_BYTES>>>(
            hh, hl, w2h, y, nullptr, nullptr);

    combine_kernel<<<T_, 256>>>(out);
}